// round 6
// baseline (speedup 1.0000x reference)
#include <cuda_runtime.h>

// KNNInterpolate, 2-pass latency-split:
//   weights: 2 queries per thread (deep MLP on point gathers); writes packed
//            idx4 / w4 metadata.
//   gather:  4 queries per warp: 8 broadcast meta loads -> 12 independent
//            row gathers in flight -> FMA -> 4 streaming stores.
//
// Inputs (metadata order):
//   d_in[0] s_feats          float32 [65536, 128]
//   d_in[1] q_points         float32 [262144, 3]
//   d_in[2] s_points         float32 [65536, 3]
//   d_in[3] neighbor_indices int32   [262144, 3]
// Output: float32 [262144, 128]

#define C_FEAT 128
#define N_SRC 65536
#define M_QRY 262144
#define EPS 1e-8f

__device__ int4   g_idx4[M_QRY];     // i0,i1,i2,pad
__device__ float4 g_w4[M_QRY];       // w0,w1,w2,pad

__device__ __forceinline__ float wgt3(const float* __restrict__ sp, int i,
                                      float qx, float qy, float qz)
{
    float dx = qx - __ldg(sp + 3ll * i + 0);
    float dy = qy - __ldg(sp + 3ll * i + 1);
    float dz = qz - __ldg(sp + 3ll * i + 2);
    return 1.0f / (dx * dx + dy * dy + dz * dz + EPS);
}

// Two queries per thread: all 6 idx + 18 point loads independent -> deep MLP.
__global__ __launch_bounds__(256) void weights_kernel(
    const float* __restrict__ q_points,
    const float* __restrict__ s_points,
    const int* __restrict__ nidx,
    int n_dual)
{
    int t = blockIdx.x * blockDim.x + threadIdx.x;
    if (t >= n_dual) return;
    const int m0 = 2 * t;
    const int m1 = m0 + 1;

    const int ia0 = __ldg(nidx + 3ll * m0 + 0);
    const int ia1 = __ldg(nidx + 3ll * m0 + 1);
    const int ia2 = __ldg(nidx + 3ll * m0 + 2);
    const int ib0 = __ldg(nidx + 3ll * m1 + 0);
    const int ib1 = __ldg(nidx + 3ll * m1 + 1);
    const int ib2 = __ldg(nidx + 3ll * m1 + 2);

    const float ax = __ldg(q_points + 3ll * m0 + 0);
    const float ay = __ldg(q_points + 3ll * m0 + 1);
    const float az = __ldg(q_points + 3ll * m0 + 2);
    const float bx = __ldg(q_points + 3ll * m1 + 0);
    const float by = __ldg(q_points + 3ll * m1 + 1);
    const float bz = __ldg(q_points + 3ll * m1 + 2);

    float wa0 = wgt3(s_points, ia0, ax, ay, az);
    float wa1 = wgt3(s_points, ia1, ax, ay, az);
    float wa2 = wgt3(s_points, ia2, ax, ay, az);
    float wb0 = wgt3(s_points, ib0, bx, by, bz);
    float wb1 = wgt3(s_points, ib1, bx, by, bz);
    float wb2 = wgt3(s_points, ib2, bx, by, bz);

    const float sa = 1.0f / (wa0 + wa1 + wa2);
    const float sb = 1.0f / (wb0 + wb1 + wb2);

    g_idx4[m0] = make_int4(ia0, ia1, ia2, 0);
    g_w4[m0] = make_float4(wa0 * sa, wa1 * sa, wa2 * sa, 0.0f);
    g_idx4[m1] = make_int4(ib0, ib1, ib2, 0);
    g_w4[m1] = make_float4(wb0 * sb, wb1 * sb, wb2 * sb, 0.0f);
}

__device__ __forceinline__ float4 wsum(float4 a, float4 b, float4 c, float4 w)
{
    float4 r;
    r.x = w.x * a.x; r.y = w.x * a.y; r.z = w.x * a.z; r.w = w.x * a.w;
    r.x = fmaf(w.y, b.x, r.x); r.y = fmaf(w.y, b.y, r.y);
    r.z = fmaf(w.y, b.z, r.z); r.w = fmaf(w.y, b.w, r.w);
    r.x = fmaf(w.z, c.x, r.x); r.y = fmaf(w.z, c.y, r.y);
    r.z = fmaf(w.z, c.z, r.z); r.w = fmaf(w.z, c.w, r.w);
    return r;
}

// One warp per FOUR queries: 12 independent row gathers in flight.
__global__ __launch_bounds__(256, 4) void gather_kernel(
    const float* __restrict__ s_feats,
    float4* __restrict__ out,
    int n_quad)
{
    const int quad = (int)((blockIdx.x * blockDim.x + threadIdx.x) >> 5);
    const int lane = threadIdx.x & 31;
    if (quad >= n_quad) return;

    const int m0 = 4 * quad;

    // broadcast meta loads (8 independent LDG.128)
    const int4 iv0 = __ldg(&g_idx4[m0 + 0]);
    const int4 iv1 = __ldg(&g_idx4[m0 + 1]);
    const int4 iv2 = __ldg(&g_idx4[m0 + 2]);
    const int4 iv3 = __ldg(&g_idx4[m0 + 3]);
    const float4 wv0 = __ldg(&g_w4[m0 + 0]);
    const float4 wv1 = __ldg(&g_w4[m0 + 1]);
    const float4 wv2 = __ldg(&g_w4[m0 + 2]);
    const float4 wv3 = __ldg(&g_w4[m0 + 3]);

    const float4* sfl = (const float4*)s_feats + lane;  // lane-offset base

    // twelve independent row gathers
    const float4 a0 = __ldg(sfl + (long long)iv0.x * (C_FEAT / 4));
    const float4 b0 = __ldg(sfl + (long long)iv0.y * (C_FEAT / 4));
    const float4 c0 = __ldg(sfl + (long long)iv0.z * (C_FEAT / 4));
    const float4 a1 = __ldg(sfl + (long long)iv1.x * (C_FEAT / 4));
    const float4 b1 = __ldg(sfl + (long long)iv1.y * (C_FEAT / 4));
    const float4 c1 = __ldg(sfl + (long long)iv1.z * (C_FEAT / 4));
    const float4 a2 = __ldg(sfl + (long long)iv2.x * (C_FEAT / 4));
    const float4 b2 = __ldg(sfl + (long long)iv2.y * (C_FEAT / 4));
    const float4 c2 = __ldg(sfl + (long long)iv2.z * (C_FEAT / 4));
    const float4 a3 = __ldg(sfl + (long long)iv3.x * (C_FEAT / 4));
    const float4 b3 = __ldg(sfl + (long long)iv3.y * (C_FEAT / 4));
    const float4 c3 = __ldg(sfl + (long long)iv3.z * (C_FEAT / 4));

    float4* o = out + (long long)m0 * (C_FEAT / 4) + lane;
    __stcs(o + 0 * (C_FEAT / 4), wsum(a0, b0, c0, wv0));
    __stcs(o + 1 * (C_FEAT / 4), wsum(a1, b1, c1, wv1));
    __stcs(o + 2 * (C_FEAT / 4), wsum(a2, b2, c2, wv2));
    __stcs(o + 3 * (C_FEAT / 4), wsum(a3, b3, c3, wv3));
}

extern "C" void kernel_launch(void* const* d_in, const int* in_sizes, int n_in,
                              void* d_out, int out_size)
{
    const float* s_feats = (const float*)d_in[0];
    const float* q_points = (const float*)d_in[1];
    const float* s_points = (const float*)d_in[2];
    const int* nidx = (const int*)d_in[3];
    float4* out = (float4*)d_out;

    const int M = in_sizes[1] / 3;   // 262144
    const int n_dual = M / 2;
    const int n_quad = M / 4;

    weights_kernel<<<(n_dual + 255) / 256, 256>>>(q_points, s_points, nidx, n_dual);

    const int warps_per_block = 8;   // 256 threads
    const int blocks = (n_quad + warps_per_block - 1) / warps_per_block;
    gather_kernel<<<blocks, warps_per_block * 32>>>(s_feats, out, n_quad);
}